// round 1
// baseline (speedup 1.0000x reference)
#include <cuda_runtime.h>
#include <math_constants.h>

// Problem constants (fixed shapes per reference)
#define MAXN 50048
#define MAXE 400000
#define DD   256

// ---------------- scratch (static device globals; no allocs) ----------------
__device__ float g_q   [MAXN * DD];
__device__ float g_k   [MAXN * DD];
__device__ float g_v   [MAXN * DD];
__device__ float g_skip[MAXN * DD];
__device__ float g_lin [MAXN * DD];
__device__ float g_agg [MAXN * DD];
__device__ float g_hA  [MAXN * DD];
__device__ float g_hB  [MAXN * DD];
__device__ int   g_deg   [MAXN];
__device__ int   g_rowptr[MAXN + 1];
__device__ int   g_cursor[MAXN];
__device__ int   g_col   [MAXE];

// ---------------- CSR build ----------------
__global__ void zero_int_kernel(int* p, int n) {
    int i = blockIdx.x * blockDim.x + threadIdx.x;
    if (i < n) p[i] = 0;
}

__global__ void count_deg_kernel(const int* __restrict__ dst, int* deg, int E) {
    int i = blockIdx.x * blockDim.x + threadIdx.x;
    if (i < E) atomicAdd(&deg[dst[i]], 1);
}

// single-block exclusive scan (n up to ~64k, 1024 threads, chunked)
__global__ void exscan_kernel(const int* __restrict__ deg, int* rowptr, int n) {
    __shared__ int warpsums[32];
    __shared__ int carry_s;
    int tid = threadIdx.x, lane = tid & 31, wid = tid >> 5;
    if (tid == 0) carry_s = 0;
    __syncthreads();
    for (int base = 0; base < n; base += 1024) {
        int carry = carry_s;
        int i = base + tid;
        int v = (i < n) ? deg[i] : 0;
        // inclusive warp scan
        int x = v;
        #pragma unroll
        for (int o = 1; o < 32; o <<= 1) {
            int y = __shfl_up_sync(0xffffffffu, x, o);
            if (lane >= o) x += y;
        }
        if (lane == 31) warpsums[wid] = x;
        __syncthreads();
        if (wid == 0) {
            int s = warpsums[lane];
            #pragma unroll
            for (int o = 1; o < 32; o <<= 1) {
                int y = __shfl_up_sync(0xffffffffu, s, o);
                if (lane >= o) s += y;
            }
            warpsums[lane] = s;
        }
        __syncthreads();
        int block_excl = (wid > 0) ? warpsums[wid - 1] : 0;
        int incl = x + block_excl;
        if (i < n) rowptr[i] = carry + incl - v;   // exclusive
        int total = warpsums[31];
        __syncthreads();
        if (tid == 0) carry_s = carry + total;
        __syncthreads();
    }
    if (tid == 0) rowptr[n] = carry_s;
}

__global__ void copy_int_kernel(const int* __restrict__ a, int* b, int n) {
    int i = blockIdx.x * blockDim.x + threadIdx.x;
    if (i < n) b[i] = a[i];
}

__global__ void scatter_kernel(const int* __restrict__ src, const int* __restrict__ dst,
                               int* cursor, int* col, int E) {
    int i = blockIdx.x * blockDim.x + threadIdx.x;
    if (i < E) {
        int d = dst[i];
        int pos = atomicAdd(&cursor[d], 1);
        col[pos] = src[i];
    }
}

// ---------------- SGEMM: Y[N,M] = X[N,K] @ W[K,M] + bias[M] ----------------
// 128x128 tile, BK=16, 256 threads, 8x8 per thread (split 4+4 fragments)
#define BM 128
#define BN 128
#define BK 16

__global__ void sgemm_kernel(const float* __restrict__ X, const float* __restrict__ W,
                             const float* __restrict__ bias, float* __restrict__ Y,
                             int Nrows, int Kdim, int Mcols) {
    __shared__ __align__(16) float Xs[BK][BM];
    __shared__ __align__(16) float Ws[BK][BN];
    int tid = threadIdx.x;
    int tx = tid & 15, ty = tid >> 4;
    int rowTile = blockIdx.x * BM;
    int colTile = blockIdx.y * BN;

    float acc[8][8];
    #pragma unroll
    for (int r = 0; r < 8; r++)
        #pragma unroll
        for (int c = 0; c < 8; c++) acc[r][c] = 0.f;

    for (int k0 = 0; k0 < Kdim; k0 += BK) {
        // load X tile (transposed into Xs[k][m]); 512 float4 total
        #pragma unroll
        for (int it = 0; it < 2; it++) {
            int f = tid + it * 256;
            int r  = f >> 2;          // 0..127
            int kc = (f & 3) << 2;    // 0,4,8,12
            int grow = rowTile + r;
            float4 val = make_float4(0.f, 0.f, 0.f, 0.f);
            if (grow < Nrows) val = *(const float4*)&X[(size_t)grow * Kdim + k0 + kc];
            Xs[kc + 0][r] = val.x; Xs[kc + 1][r] = val.y;
            Xs[kc + 2][r] = val.z; Xs[kc + 3][r] = val.w;
        }
        // load W tile
        #pragma unroll
        for (int it = 0; it < 2; it++) {
            int f = tid + it * 256;
            int k  = f >> 5;          // 0..15
            int nc = (f & 31) << 2;   // 0..124
            int gcol = colTile + nc;
            float4 val = make_float4(0.f, 0.f, 0.f, 0.f);
            if (gcol < Mcols) val = *(const float4*)&W[(size_t)(k0 + k) * Mcols + gcol];
            *(float4*)&Ws[k][nc] = val;
        }
        __syncthreads();
        #pragma unroll
        for (int k = 0; k < BK; k++) {
            const float4* xs4 = reinterpret_cast<const float4*>(&Xs[k][0]);
            const float4* ws4 = reinterpret_cast<const float4*>(&Ws[k][0]);
            float4 a0 = xs4[ty], a1 = xs4[16 + ty];
            float4 b0 = ws4[tx], b1 = ws4[16 + tx];
            float a[8] = {a0.x, a0.y, a0.z, a0.w, a1.x, a1.y, a1.z, a1.w};
            float b[8] = {b0.x, b0.y, b0.z, b0.w, b1.x, b1.y, b1.z, b1.w};
            #pragma unroll
            for (int r = 0; r < 8; r++)
                #pragma unroll
                for (int c = 0; c < 8; c++)
                    acc[r][c] += a[r] * b[c];
        }
        __syncthreads();
    }

    // store with bias
    #pragma unroll
    for (int ri = 0; ri < 2; ri++) {
        #pragma unroll
        for (int i = 0; i < 4; i++) {
            int row = rowTile + ri * 64 + ty * 4 + i;
            if (row >= Nrows) continue;
            #pragma unroll
            for (int cj = 0; cj < 2; cj++) {
                int n0 = colTile + cj * 64 + tx * 4;
                if (n0 >= Mcols) continue;
                float4 o;
                o.x = acc[ri * 4 + i][cj * 4 + 0] + bias[n0 + 0];
                o.y = acc[ri * 4 + i][cj * 4 + 1] + bias[n0 + 1];
                o.z = acc[ri * 4 + i][cj * 4 + 2] + bias[n0 + 2];
                o.w = acc[ri * 4 + i][cj * 4 + 3] + bias[n0 + 3];
                *(float4*)&Y[(size_t)row * Mcols + n0] = o;
            }
        }
    }
}

// ---------------- edge attention (layers): H=4 heads, C=64 ch ----------------
// one warp per (node, head); online softmax over incoming neighbors
__global__ void edge_attn_kernel(const float* __restrict__ q, const float* __restrict__ k,
                                 const float* __restrict__ v,
                                 const int* __restrict__ rowptr, const int* __restrict__ col,
                                 float* __restrict__ agg, int Nn) {
    int gw = (blockIdx.x * blockDim.x + threadIdx.x) >> 5;
    int lane = threadIdx.x & 31;
    int node = gw >> 2;
    int head = gw & 3;
    if (node >= Nn) return;
    int base = node * 256 + head * 64 + lane * 2;
    float2 q2 = *(const float2*)&q[base];
    int e0 = rowptr[node], e1 = rowptr[node + 1];
    float m = -CUDART_INF_F, ssum = 0.f;
    float2 acc = make_float2(0.f, 0.f);
    for (int e = e0; e < e1; e++) {
        int src = col[e];
        int sb = src * 256 + head * 64 + lane * 2;
        float2 k2 = *(const float2*)&k[sb];
        float part = q2.x * k2.x + q2.y * k2.y;
        #pragma unroll
        for (int o = 16; o > 0; o >>= 1) part += __shfl_xor_sync(0xffffffffu, part, o);
        float score = part * 0.125f;           // 1/sqrt(64)
        float newm = fmaxf(m, score);
        float scale = __expf(m - newm);        // exp(-inf)=0 on first iter
        float p = __expf(score - newm);
        ssum = ssum * scale + p;
        float2 v2 = *(const float2*)&v[sb];
        acc.x = acc.x * scale + p * v2.x;
        acc.y = acc.y * scale + p * v2.y;
        m = newm;
    }
    float inv = (ssum > 0.f) ? (1.f / ssum) : 0.f;
    acc.x *= inv; acc.y *= inv;
    *(float2*)&agg[base] = acc;
}

// ---------------- combine + elu + layernorm (layers) ----------------
// one warp per node, 8 elements per lane
__global__ void combine_ln_kernel(const float* __restrict__ agg, const float* __restrict__ skip,
                                  const float* __restrict__ lin,
                                  const float* __restrict__ g, const float* __restrict__ b,
                                  float* __restrict__ hout, int Nn) {
    int node = (blockIdx.x * blockDim.x + threadIdx.x) >> 5;
    int lane = threadIdx.x & 31;
    if (node >= Nn) return;
    int base = node * 256;
    float t[8];
    float sum = 0.f;
    #pragma unroll
    for (int r = 0; r < 8; r++) {
        int idx = base + r * 32 + lane;
        float c = agg[idx] + skip[idx] + lin[idx];
        float e = (c > 0.f) ? c : expm1f(c);
        t[r] = e; sum += e;
    }
    #pragma unroll
    for (int o = 16; o > 0; o >>= 1) sum += __shfl_xor_sync(0xffffffffu, sum, o);
    float mu = sum * (1.f / 256.f);
    float var = 0.f;
    #pragma unroll
    for (int r = 0; r < 8; r++) { float d = t[r] - mu; var += d * d; }
    #pragma unroll
    for (int o = 16; o > 0; o >>= 1) var += __shfl_xor_sync(0xffffffffu, var, o);
    var *= (1.f / 256.f);
    float inv = rsqrtf(var + 1e-5f);
    #pragma unroll
    for (int r = 0; r < 8; r++) {
        int j = r * 32 + lane;
        hout[base + j] = (t[r] - mu) * inv * g[j] + b[j];
    }
}

// ---------------- final edge attention: HF=4 heads, C=16 ch ----------------
// one warp per node; 8-lane group per head, 2 channels per lane
__global__ void edge_attn_final_kernel(const float* __restrict__ q, const float* __restrict__ k,
                                       const float* __restrict__ v,
                                       const int* __restrict__ rowptr, const int* __restrict__ col,
                                       float* __restrict__ agg, int Nn) {
    int node = (blockIdx.x * blockDim.x + threadIdx.x) >> 5;
    int lane = threadIdx.x & 31;
    if (node >= Nn) return;
    int group = lane >> 3;     // head
    int lg = lane & 7;
    int base = node * 64 + group * 16 + lg * 2;
    float2 q2 = *(const float2*)&q[base];
    int e0 = rowptr[node], e1 = rowptr[node + 1];
    float m = -CUDART_INF_F, ssum = 0.f;
    float2 acc = make_float2(0.f, 0.f);
    for (int e = e0; e < e1; e++) {
        int src = col[e];
        int sb = src * 64 + group * 16 + lg * 2;
        float2 k2 = *(const float2*)&k[sb];
        float part = q2.x * k2.x + q2.y * k2.y;
        #pragma unroll
        for (int o = 4; o > 0; o >>= 1) part += __shfl_xor_sync(0xffffffffu, part, o);
        float score = part * 0.25f;            // 1/sqrt(16)
        float newm = fmaxf(m, score);
        float scale = __expf(m - newm);
        float p = __expf(score - newm);
        ssum = ssum * scale + p;
        float2 v2 = *(const float2*)&v[sb];
        acc.x = acc.x * scale + p * v2.x;
        acc.y = acc.y * scale + p * v2.y;
        m = newm;
    }
    float inv = (ssum > 0.f) ? (1.f / ssum) : 0.f;
    acc.x *= inv; acc.y *= inv;
    *(float2*)&agg[base] = acc;
}

// ---------------- final combine: mean heads + skip + lin + LN(16) ----------------
__global__ void final_combine_kernel(const float* __restrict__ aggF, const float* __restrict__ skipF,
                                     const float* __restrict__ linF,
                                     const float* __restrict__ g, const float* __restrict__ b,
                                     float* __restrict__ out, int Nn) {
    int t = blockIdx.x * blockDim.x + threadIdx.x;
    int node = t >> 4;
    int c = t & 15;
    if (node >= Nn) return;
    float val = 0.25f * (aggF[node * 64 + c] + aggF[node * 64 + 16 + c] +
                         aggF[node * 64 + 32 + c] + aggF[node * 64 + 48 + c])
              + skipF[node * 16 + c] + linF[node * 16 + c];
    float sum = val;
    #pragma unroll
    for (int o = 8; o > 0; o >>= 1) sum += __shfl_xor_sync(0xffffffffu, sum, o);
    float mu = sum * (1.f / 16.f);
    float d = val - mu;
    float var = d * d;
    #pragma unroll
    for (int o = 8; o > 0; o >>= 1) var += __shfl_xor_sync(0xffffffffu, var, o);
    var *= (1.f / 16.f);
    out[node * 16 + c] = (val - mu) * rsqrtf(var + 1e-5f) * g[c] + b[c];
}

// ---------------- host launch ----------------
static inline int cdiv(int a, int b) { return (a + b - 1) / b; }

static void launch_gemm(const float* X, const float* W, const float* bias, float* Y,
                        int n, int kd, int m) {
    dim3 grid(cdiv(n, BM), cdiv(m, BN));
    sgemm_kernel<<<grid, 256>>>(X, W, bias, Y, n, kd, m);
}

extern "C" void kernel_launch(void* const* d_in, const int* in_sizes, int n_in,
                              void* d_out, int out_size) {
    const float* x    = (const float*)d_in[0];
    const int*   ei   = (const int*)  d_in[1];
    const float* Wq   = (const float*)d_in[2];
    const float* bq   = (const float*)d_in[3];
    const float* Wk   = (const float*)d_in[4];
    const float* bk   = (const float*)d_in[5];
    const float* Wv   = (const float*)d_in[6];
    const float* bv   = (const float*)d_in[7];
    const float* Ws   = (const float*)d_in[8];
    const float* bs   = (const float*)d_in[9];
    const float* lnG  = (const float*)d_in[10];
    const float* lnB  = (const float*)d_in[11];
    const float* linW = (const float*)d_in[12];
    const float* linB = (const float*)d_in[13];
    const float* fWq  = (const float*)d_in[14];
    const float* fbq  = (const float*)d_in[15];
    const float* fWk  = (const float*)d_in[16];
    const float* fbk  = (const float*)d_in[17];
    const float* fWv  = (const float*)d_in[18];
    const float* fbv  = (const float*)d_in[19];
    const float* fWs  = (const float*)d_in[20];
    const float* fbs  = (const float*)d_in[21];
    const float* flnG = (const float*)d_in[22];
    const float* flnB = (const float*)d_in[23];
    const float* flinW= (const float*)d_in[24];
    const float* flinB= (const float*)d_in[25];
    float* out = (float*)d_out;

    int N = in_sizes[0] / DD;     // 50000
    int E = in_sizes[1] / 2;      // 400000

    float *p_q, *p_k, *p_v, *p_skip, *p_lin, *p_agg, *p_hA, *p_hB;
    int *p_deg, *p_rowptr, *p_cursor, *p_col;
    cudaGetSymbolAddress((void**)&p_q,    g_q);
    cudaGetSymbolAddress((void**)&p_k,    g_k);
    cudaGetSymbolAddress((void**)&p_v,    g_v);
    cudaGetSymbolAddress((void**)&p_skip, g_skip);
    cudaGetSymbolAddress((void**)&p_lin,  g_lin);
    cudaGetSymbolAddress((void**)&p_agg,  g_agg);
    cudaGetSymbolAddress((void**)&p_hA,   g_hA);
    cudaGetSymbolAddress((void**)&p_hB,   g_hB);
    cudaGetSymbolAddress((void**)&p_deg,    g_deg);
    cudaGetSymbolAddress((void**)&p_rowptr, g_rowptr);
    cudaGetSymbolAddress((void**)&p_cursor, g_cursor);
    cudaGetSymbolAddress((void**)&p_col,    g_col);

    const int* src = ei;       // edge_index[0]
    const int* dst = ei + E;   // edge_index[1]

    // --- CSR build (by dst) ---
    zero_int_kernel<<<cdiv(N, 256), 256>>>(p_deg, N);
    count_deg_kernel<<<cdiv(E, 256), 256>>>(dst, p_deg, E);
    exscan_kernel<<<1, 1024>>>(p_deg, p_rowptr, N);
    copy_int_kernel<<<cdiv(N, 256), 256>>>(p_rowptr, p_cursor, N);
    scatter_kernel<<<cdiv(E, 256), 256>>>(src, dst, p_cursor, p_col, E);

    // --- 3 TransformerConv layers ---
    const float* hin = x;
    float* houts[3] = { p_hA, p_hB, p_hA };
    for (int i = 0; i < 3; i++) {
        const float* wq = Wq + (size_t)i * DD * DD;
        const float* wk = Wk + (size_t)i * DD * DD;
        const float* wv = Wv + (size_t)i * DD * DD;
        const float* ws = Ws + (size_t)i * DD * DD;
        const float* wl = linW + (size_t)i * DD * DD;
        launch_gemm(hin, wq, bq + i * DD, p_q,    N, DD, DD);
        launch_gemm(hin, wk, bk + i * DD, p_k,    N, DD, DD);
        launch_gemm(hin, wv, bv + i * DD, p_v,    N, DD, DD);
        launch_gemm(hin, ws, bs + i * DD, p_skip, N, DD, DD);
        launch_gemm(hin, wl, linB + i * DD, p_lin, N, DD, DD);
        edge_attn_kernel<<<cdiv(N * 4 * 32, 256), 256>>>(p_q, p_k, p_v, p_rowptr, p_col, p_agg, N);
        combine_ln_kernel<<<cdiv(N * 32, 256), 256>>>(p_agg, p_skip, p_lin,
                                                      lnG + i * DD, lnB + i * DD, houts[i], N);
        hin = houts[i];
    }

    // --- final conv (HF=4, CLS=16, mean over heads) ---
    launch_gemm(hin, fWq, fbq, p_q,    N, DD, 64);
    launch_gemm(hin, fWk, fbk, p_k,    N, DD, 64);
    launch_gemm(hin, fWv, fbv, p_v,    N, DD, 64);
    launch_gemm(hin, fWs, fbs, p_skip, N, DD, 16);
    launch_gemm(hin, flinW, flinB, p_lin, N, DD, 16);
    edge_attn_final_kernel<<<cdiv(N * 32, 256), 256>>>(p_q, p_k, p_v, p_rowptr, p_col, p_agg, N);
    final_combine_kernel<<<cdiv(N * 16, 256), 256>>>(p_agg, p_skip, p_lin, flnG, flnB, out, N);
}

// round 4
// speedup vs baseline: 1.7893x; 1.7893x over previous
#include <cuda_runtime.h>
#include <cuda_bf16.h>
#include <math_constants.h>
#include <stdint.h>

// Problem constants (fixed shapes per reference)
#define MAXN 50048
#define MAXE 400000
#define DD   256

// ---------------- scratch (static device globals; no allocs) ----------------
__device__ float g_q   [MAXN * DD];
__device__ float g_k   [MAXN * DD];
__device__ float g_v   [MAXN * DD];
__device__ float g_skip[MAXN * DD];
__device__ float g_lin [MAXN * DD];
__device__ float g_agg [MAXN * DD];
__device__ __nv_bfloat16 g_hhi[MAXN * DD];
__device__ __nv_bfloat16 g_hlo[MAXN * DD];
// transposed split weights: 15 layer mats (65536) + 3x16384 + 2x4096
#define WOFF_F   (15 * 65536)
#define WTOTAL   (WOFF_F + 3 * 16384 + 2 * 4096)
__device__ __nv_bfloat16 g_whi[WTOTAL];
__device__ __nv_bfloat16 g_wlo[WTOTAL];
__device__ int   g_deg   [MAXN];
__device__ int   g_rowptr[MAXN + 1];
__device__ int   g_cursor[MAXN];
__device__ int   g_col   [MAXE];

// ---------------- CSR build ----------------
__global__ void zero_int_kernel(int* p, int n) {
    int i = blockIdx.x * blockDim.x + threadIdx.x;
    if (i < n) p[i] = 0;
}

__global__ void count_deg_kernel(const int* __restrict__ dst, int* deg, int E) {
    int i = blockIdx.x * blockDim.x + threadIdx.x;
    if (i < E) atomicAdd(&deg[dst[i]], 1);
}

__global__ void exscan_kernel(const int* __restrict__ deg, int* rowptr, int n) {
    __shared__ int warpsums[32];
    __shared__ int carry_s;
    int tid = threadIdx.x, lane = tid & 31, wid = tid >> 5;
    if (tid == 0) carry_s = 0;
    __syncthreads();
    for (int base = 0; base < n; base += 1024) {
        int carry = carry_s;
        int i = base + tid;
        int v = (i < n) ? deg[i] : 0;
        int x = v;
        #pragma unroll
        for (int o = 1; o < 32; o <<= 1) {
            int y = __shfl_up_sync(0xffffffffu, x, o);
            if (lane >= o) x += y;
        }
        if (lane == 31) warpsums[wid] = x;
        __syncthreads();
        if (wid == 0) {
            int s = warpsums[lane];
            #pragma unroll
            for (int o = 1; o < 32; o <<= 1) {
                int y = __shfl_up_sync(0xffffffffu, s, o);
                if (lane >= o) s += y;
            }
            warpsums[lane] = s;
        }
        __syncthreads();
        int block_excl = (wid > 0) ? warpsums[wid - 1] : 0;
        int incl = x + block_excl;
        if (i < n) rowptr[i] = carry + incl - v;
        int total = warpsums[31];
        __syncthreads();
        if (tid == 0) carry_s = carry + total;
        __syncthreads();
    }
    if (tid == 0) rowptr[n] = carry_s;
}

__global__ void copy_int_kernel(const int* __restrict__ a, int* b, int n) {
    int i = blockIdx.x * blockDim.x + threadIdx.x;
    if (i < n) b[i] = a[i];
}

__global__ void scatter_kernel(const int* __restrict__ src, const int* __restrict__ dst,
                               int* cursor, int* col, int E) {
    int i = blockIdx.x * blockDim.x + threadIdx.x;
    if (i < E) {
        int d = dst[i];
        int pos = atomicAdd(&cursor[d], 1);
        col[pos] = src[i];
    }
}

// ---------------- split conversions ----------------
__device__ __forceinline__ void bf16_split(float f, __nv_bfloat16& h, __nv_bfloat16& l) {
    h = __float2bfloat16(f);
    l = __float2bfloat16(f - __bfloat162float(h));
}

// x [N,256] fp32 -> hi/lo bf16 same layout
__global__ void convert_x_kernel(const float* __restrict__ in,
                                 __nv_bfloat16* __restrict__ hi,
                                 __nv_bfloat16* __restrict__ lo, int n) {
    int i = blockIdx.x * blockDim.x + threadIdx.x;
    if (i < n) {
        __nv_bfloat16 h, l;
        bf16_split(in[i], h, l);
        hi[i] = h; lo[i] = l;
    }
}

// W [256, M] fp32 row-major -> Wt [M, 256] hi/lo bf16 (k contiguous)
__global__ void convert_w_kernel(const float* __restrict__ W,
                                 __nv_bfloat16* __restrict__ hi,
                                 __nv_bfloat16* __restrict__ lo, int M) {
    int idx = blockIdx.x * blockDim.x + threadIdx.x;
    if (idx < M * 256) {
        int kk = idx & 255;
        int m  = idx >> 8;
        __nv_bfloat16 h, l;
        bf16_split(W[kk * M + m], h, l);
        hi[idx] = h; lo[idx] = l;
    }
}

// ---------------- bf16x3 tensor-core GEMM ----------------
// Y[N,M] = X[N,256] @ W[256,M] + bias[M], with X,W pre-split into bf16 hi/lo.
// Computes hi*hi + hi*lo + lo*hi with fp32 accumulation (near-fp32 accuracy).
// A: hi/lo [N,256] bf16 row-major. B: hi/lo [M,256] bf16 (k contiguous).
// 128x128 block tile, TBK=32 (2 x k16 MMA steps), 256 threads = 8 warps (4Mx2N),
// warp tile 32x64. Smem row stride 20 words (40 bf16) -> conflict-free frags.

#define TBM    128
#define TBK    32
#define ROW_W  20              // words per smem row (16 data + 4 pad)
#define A_W    (128 * ROW_W)   // 2560 words per tile buffer
#define SMEM_WORDS (8 * A_W)   // AsHi/AsLo/BsHi/BsLo x 2 buffers = 81920 B

__device__ __forceinline__ void cp16(uint32_t saddr, const void* gaddr, bool pred) {
    int sz = pred ? 16 : 0;
    asm volatile("cp.async.ca.shared.global [%0], [%1], 16, %2;\n"
                 :: "r"(saddr), "l"(gaddr), "r"(sz));
}
__device__ __forceinline__ void cp_commit() {
    asm volatile("cp.async.commit_group;\n" ::: "memory");
}
template <int NN>
__device__ __forceinline__ void cp_wait() {
    asm volatile("cp.async.wait_group %0;\n" :: "n"(NN) : "memory");
}

__device__ __forceinline__ void mma_bf16(float c[4], uint32_t a0, uint32_t a1,
                                         uint32_t a2, uint32_t a3,
                                         uint32_t b0, uint32_t b1) {
    asm volatile(
        "mma.sync.aligned.m16n8k16.row.col.f32.bf16.bf16.f32 "
        "{%0,%1,%2,%3}, {%4,%5,%6,%7}, {%8,%9}, {%0,%1,%2,%3};\n"
        : "+f"(c[0]), "+f"(c[1]), "+f"(c[2]), "+f"(c[3])
        : "r"(a0), "r"(a1), "r"(a2), "r"(a3), "r"(b0), "r"(b1));
}

__global__ void __launch_bounds__(256, 2)
gemm_bf16x3_kernel(const __nv_bfloat16* __restrict__ Xhi, const __nv_bfloat16* __restrict__ Xlo,
                   const __nv_bfloat16* __restrict__ Whi, const __nv_bfloat16* __restrict__ Wlo,
                   const float* __restrict__ bias, float* __restrict__ Y,
                   int Nrows, int Mcols) {
    extern __shared__ uint32_t smw[];
    // regions: [AsHi 2][AsLo 2][BsHi 2][BsLo 2], each A_W words
    uint32_t base_u = (uint32_t)__cvta_generic_to_shared(smw);

    int tid = threadIdx.x;
    int lane = tid & 31, wid = tid >> 5;
    int rowTile = blockIdx.x * TBM;
    int colTile = blockIdx.y * 128;
    int warpRow = (wid & 3) * 32;
    int warpCol = (wid >> 2) * 64;

    float acc[2][8][4];
    #pragma unroll
    for (int mf = 0; mf < 2; mf++)
        #pragma unroll
        for (int nf = 0; nf < 8; nf++)
            #pragma unroll
            for (int i = 0; i < 4; i++) acc[mf][nf][i] = 0.f;

    auto stage = [&](int t, int buf) {
        int k0 = t * TBK;
        #pragma unroll
        for (int i = 0; i < 2; i++) {
            int ch = tid + i * 256;          // 0..511
            int r = ch >> 2;                 // 0..127
            int c = ch & 3;                  // 16B chunk within row
            bool aok = (rowTile + r) < Nrows;
            size_t goff = (size_t)(rowTile + r) * 256 + k0 + c * 8;
            uint32_t soff = (uint32_t)(buf * A_W + r * ROW_W + c * 4) * 4u;
            cp16(base_u + soff, Xhi + goff, aok);
            cp16(base_u + (uint32_t)(2 * A_W) * 4u + soff, Xlo + goff, aok);
            bool bok = (colTile + r) < Mcols;
            size_t gboff = (size_t)(colTile + r) * 256 + k0 + c * 8;
            cp16(base_u + (uint32_t)(4 * A_W) * 4u + soff, Whi + gboff, bok);
            cp16(base_u + (uint32_t)(6 * A_W) * 4u + soff, Wlo + gboff, bok);
        }
        cp_commit();
    };

    stage(0, 0);

    const int NT = 256 / TBK;  // 8
    for (int t = 0; t < NT; t++) {
        int buf = t & 1;
        if (t + 1 < NT) stage(t + 1, buf ^ 1);
        if (t + 1 < NT) cp_wait<1>(); else cp_wait<0>();
        __syncthreads();

        const uint32_t* AH = smw + buf * A_W;
        const uint32_t* AL = smw + 2 * A_W + buf * A_W;
        const uint32_t* BH = smw + 4 * A_W + buf * A_W;
        const uint32_t* BL = smw + 6 * A_W + buf * A_W;

        #pragma unroll
        for (int s = 0; s < 2; s++) {      // two k16 steps
            int kb = s * 8;
            uint32_t ahi[2][4], alo[2][4];
            #pragma unroll
            for (int mf = 0; mf < 2; mf++) {
                int r0 = warpRow + mf * 16 + (lane >> 2);
                int w0 = r0 * ROW_W + kb + (lane & 3);
                ahi[mf][0] = AH[w0];
                ahi[mf][1] = AH[w0 + 8 * ROW_W];
                ahi[mf][2] = AH[w0 + 4];
                ahi[mf][3] = AH[w0 + 4 + 8 * ROW_W];
                alo[mf][0] = AL[w0];
                alo[mf][1] = AL[w0 + 8 * ROW_W];
                alo[mf][2] = AL[w0 + 4];
                alo[mf][3] = AL[w0 + 4 + 8 * ROW_W];
            }
            #pragma unroll
            for (int nf = 0; nf < 8; nf++) {
                int n = warpCol + nf * 8 + (lane >> 2);
                int wb = n * ROW_W + kb + (lane & 3);
                uint32_t bh0 = BH[wb], bh1 = BH[wb + 4];
                uint32_t bl0 = BL[wb], bl1 = BL[wb + 4];
                #pragma unroll
                for (int mf = 0; mf < 2; mf++) {
                    mma_bf16(acc[mf][nf], ahi[mf][0], ahi[mf][1], ahi[mf][2], ahi[mf][3], bh0, bh1);
                    mma_bf16(acc[mf][nf], ahi[mf][0], ahi[mf][1], ahi[mf][2], ahi[mf][3], bl0, bl1);
                    mma_bf16(acc[mf][nf], alo[mf][0], alo[mf][1], alo[mf][2], alo[mf][3], bh0, bh1);
                }
            }
        }
        __syncthreads();
    }

    // ---- epilogue: bias + store ----
    #pragma unroll
    for (int mf = 0; mf < 2; mf++) {
        #pragma unroll
        for (int nf = 0; nf < 8; nf++) {
            int col = colTile + warpCol + nf * 8 + 2 * (lane & 3);
            if (col >= Mcols) continue;
            float bx = bias[col], by = bias[col + 1];
            int r0 = rowTile + warpRow + mf * 16 + (lane >> 2);
            if (r0 < Nrows) {
                float2 o = make_float2(acc[mf][nf][0] + bx, acc[mf][nf][1] + by);
                *(float2*)&Y[(size_t)r0 * Mcols + col] = o;
            }
            int r1 = r0 + 8;
            if (r1 < Nrows) {
                float2 o = make_float2(acc[mf][nf][2] + bx, acc[mf][nf][3] + by);
                *(float2*)&Y[(size_t)r1 * Mcols + col] = o;
            }
        }
    }
}

// ---------------- edge attention (layers): H=4 heads, C=64 ch ----------------
__global__ void edge_attn_kernel(const float* __restrict__ q, const float* __restrict__ k,
                                 const float* __restrict__ v,
                                 const int* __restrict__ rowptr, const int* __restrict__ col,
                                 float* __restrict__ agg, int Nn) {
    int gw = (blockIdx.x * blockDim.x + threadIdx.x) >> 5;
    int lane = threadIdx.x & 31;
    int node = gw >> 2;
    int head = gw & 3;
    if (node >= Nn) return;
    int base = node * 256 + head * 64 + lane * 2;
    float2 q2 = *(const float2*)&q[base];
    int e0 = rowptr[node], e1 = rowptr[node + 1];
    float m = -CUDART_INF_F, ssum = 0.f;
    float2 acc = make_float2(0.f, 0.f);
    for (int e = e0; e < e1; e++) {
        int src = col[e];
        int sb = src * 256 + head * 64 + lane * 2;
        float2 k2 = *(const float2*)&k[sb];
        float part = q2.x * k2.x + q2.y * k2.y;
        #pragma unroll
        for (int o = 16; o > 0; o >>= 1) part += __shfl_xor_sync(0xffffffffu, part, o);
        float score = part * 0.125f;
        float newm = fmaxf(m, score);
        float scale = __expf(m - newm);
        float p = __expf(score - newm);
        ssum = ssum * scale + p;
        float2 v2 = *(const float2*)&v[sb];
        acc.x = acc.x * scale + p * v2.x;
        acc.y = acc.y * scale + p * v2.y;
        m = newm;
    }
    float inv = (ssum > 0.f) ? (1.f / ssum) : 0.f;
    acc.x *= inv; acc.y *= inv;
    *(float2*)&agg[base] = acc;
}

// ---------------- combine + elu + layernorm -> split bf16 hi/lo ----------------
__global__ void combine_ln_kernel(const float* __restrict__ agg, const float* __restrict__ skip,
                                  const float* __restrict__ lin,
                                  const float* __restrict__ g, const float* __restrict__ b,
                                  __nv_bfloat16* __restrict__ hhi,
                                  __nv_bfloat16* __restrict__ hlo, int Nn) {
    int node = (blockIdx.x * blockDim.x + threadIdx.x) >> 5;
    int lane = threadIdx.x & 31;
    if (node >= Nn) return;
    int base = node * 256;
    float t[8];
    float sum = 0.f;
    #pragma unroll
    for (int r = 0; r < 8; r++) {
        int idx = base + r * 32 + lane;
        float c = agg[idx] + skip[idx] + lin[idx];
        float e = (c > 0.f) ? c : expm1f(c);
        t[r] = e; sum += e;
    }
    #pragma unroll
    for (int o = 16; o > 0; o >>= 1) sum += __shfl_xor_sync(0xffffffffu, sum, o);
    float mu = sum * (1.f / 256.f);
    float var = 0.f;
    #pragma unroll
    for (int r = 0; r < 8; r++) { float d = t[r] - mu; var += d * d; }
    #pragma unroll
    for (int o = 16; o > 0; o >>= 1) var += __shfl_xor_sync(0xffffffffu, var, o);
    var *= (1.f / 256.f);
    float inv = rsqrtf(var + 1e-5f);
    #pragma unroll
    for (int r = 0; r < 8; r++) {
        int j = r * 32 + lane;
        float val = (t[r] - mu) * inv * g[j] + b[j];
        __nv_bfloat16 h, l;
        bf16_split(val, h, l);
        hhi[base + j] = h;
        hlo[base + j] = l;
    }
}

// ---------------- final edge attention: HF=4 heads, C=16 ch ----------------
__global__ void edge_attn_final_kernel(const float* __restrict__ q, const float* __restrict__ k,
                                       const float* __restrict__ v,
                                       const int* __restrict__ rowptr, const int* __restrict__ col,
                                       float* __restrict__ agg, int Nn) {
    int node = (blockIdx.x * blockDim.x + threadIdx.x) >> 5;
    int lane = threadIdx.x & 31;
    if (node >= Nn) return;
    int group = lane >> 3;
    int lg = lane & 7;
    int base = node * 64 + group * 16 + lg * 2;
    float2 q2 = *(const float2*)&q[base];
    int e0 = rowptr[node], e1 = rowptr[node + 1];
    float m = -CUDART_INF_F, ssum = 0.f;
    float2 acc = make_float2(0.f, 0.f);
    for (int e = e0; e < e1; e++) {
        int src = col[e];
        int sb = src * 64 + group * 16 + lg * 2;
        float2 k2 = *(const float2*)&k[sb];
        float part = q2.x * k2.x + q2.y * k2.y;
        #pragma unroll
        for (int o = 4; o > 0; o >>= 1) part += __shfl_xor_sync(0xffffffffu, part, o);
        float score = part * 0.25f;
        float newm = fmaxf(m, score);
        float scale = __expf(m - newm);
        float p = __expf(score - newm);
        ssum = ssum * scale + p;
        float2 v2 = *(const float2*)&v[sb];
        acc.x = acc.x * scale + p * v2.x;
        acc.y = acc.y * scale + p * v2.y;
        m = newm;
    }
    float inv = (ssum > 0.f) ? (1.f / ssum) : 0.f;
    acc.x *= inv; acc.y *= inv;
    *(float2*)&agg[base] = acc;
}

// ---------------- final combine: mean heads + skip + lin + LN(16) ----------------
__global__ void final_combine_kernel(const float* __restrict__ aggF, const float* __restrict__ skipF,
                                     const float* __restrict__ linF,
                                     const float* __restrict__ g, const float* __restrict__ b,
                                     float* __restrict__ out, int Nn) {
    int t = blockIdx.x * blockDim.x + threadIdx.x;
    int node = t >> 4;
    int c = t & 15;
    if (node >= Nn) return;
    float val = 0.25f * (aggF[node * 64 + c] + aggF[node * 64 + 16 + c] +
                         aggF[node * 64 + 32 + c] + aggF[node * 64 + 48 + c])
              + skipF[node * 16 + c] + linF[node * 16 + c];
    float sum = val;
    #pragma unroll
    for (int o = 8; o > 0; o >>= 1) sum += __shfl_xor_sync(0xffffffffu, sum, o);
    float mu = sum * (1.f / 16.f);
    float d = val - mu;
    float var = d * d;
    #pragma unroll
    for (int o = 8; o > 0; o >>= 1) var += __shfl_xor_sync(0xffffffffu, var, o);
    var *= (1.f / 16.f);
    out[node * 16 + c] = (val - mu) * rsqrtf(var + 1e-5f) * g[c] + b[c];
}

// ---------------- host launch ----------------
static inline int cdiv(int a, int b) { return (a + b - 1) / b; }

extern "C" void kernel_launch(void* const* d_in, const int* in_sizes, int n_in,
                              void* d_out, int out_size) {
    const float* x    = (const float*)d_in[0];
    const int*   ei   = (const int*)  d_in[1];
    const float* Wq   = (const float*)d_in[2];
    const float* bq   = (const float*)d_in[3];
    const float* Wk   = (const float*)d_in[4];
    const float* bk   = (const float*)d_in[5];
    const float* Wv   = (const float*)d_in[6];
    const float* bv   = (const float*)d_in[7];
    const float* Ws   = (const float*)d_in[8];
    const float* bs   = (const float*)d_in[9];
    const float* lnG  = (const float*)d_in[10];
    const float* lnB  = (const float*)d_in[11];
    const float* linW = (const float*)d_in[12];
    const float* linB = (const float*)d_in[13];
    const float* fWq  = (const float*)d_in[14];
    const float* fbq  = (const float*)d_in[15];
    const float* fWk  = (const float*)d_in[16];
    const float* fbk  = (const float*)d_in[17];
    const float* fWv  = (const float*)d_in[18];
    const float* fbv  = (const float*)d_in[19];
    const float* fWs  = (const float*)d_in[20];
    const float* fbs  = (const float*)d_in[21];
    const float* flnG = (const float*)d_in[22];
    const float* flnB = (const float*)d_in[23];
    const float* flinW= (const float*)d_in[24];
    const float* flinB= (const float*)d_in[25];
    float* out = (float*)d_out;

    int N = in_sizes[0] / DD;     // 50000
    int E = in_sizes[1] / 2;      // 400000

    static bool smem_set = false;
    if (!smem_set) {
        cudaFuncSetAttribute(gemm_bf16x3_kernel,
                             cudaFuncAttributeMaxDynamicSharedMemorySize,
                             SMEM_WORDS * 4);
        smem_set = true;
    }

    float *p_q, *p_k, *p_v, *p_skip, *p_lin, *p_agg;
    __nv_bfloat16 *p_hhi, *p_hlo, *p_whi, *p_wlo;
    int *p_deg, *p_rowptr, *p_cursor, *p_col;
    cudaGetSymbolAddress((void**)&p_q,    g_q);
    cudaGetSymbolAddress((void**)&p_k,    g_k);
    cudaGetSymbolAddress((void**)&p_v,    g_v);
    cudaGetSymbolAddress((void**)&p_skip, g_skip);
    cudaGetSymbolAddress((void**)&p_lin,  g_lin);
    cudaGetSymbolAddress((void**)&p_agg,  g_agg);
    cudaGetSymbolAddress((void**)&p_hhi,  g_hhi);
    cudaGetSymbolAddress((void**)&p_hlo,  g_hlo);
    cudaGetSymbolAddress((void**)&p_whi,  g_whi);
    cudaGetSymbolAddress((void**)&p_wlo,  g_wlo);
    cudaGetSymbolAddress((void**)&p_deg,    g_deg);
    cudaGetSymbolAddress((void**)&p_rowptr, g_rowptr);
    cudaGetSymbolAddress((void**)&p_cursor, g_cursor);
    cudaGetSymbolAddress((void**)&p_col,    g_col);

    const int* src = ei;
    const int* dst = ei + E;

    // --- CSR build (by dst) ---
    zero_int_kernel<<<cdiv(N, 256), 256>>>(p_deg, N);
    count_deg_kernel<<<cdiv(E, 256), 256>>>(dst, p_deg, E);
    exscan_kernel<<<1, 1024>>>(p_deg, p_rowptr, N);
    copy_int_kernel<<<cdiv(N, 256), 256>>>(p_rowptr, p_cursor, N);
    scatter_kernel<<<cdiv(E, 256), 256>>>(src, dst, p_cursor, p_col, E);

    // --- weight conversion (transposed bf16 hi/lo) ---
    // layer i mats at offsets (i*5 + {0..4}) * 65536 : wq,wk,wv,ws,wl
    for (int i = 0; i < 3; i++) {
        const float* mats[5] = { Wq + (size_t)i * DD * DD, Wk + (size_t)i * DD * DD,
                                 Wv + (size_t)i * DD * DD, Ws + (size_t)i * DD * DD,
                                 linW + (size_t)i * DD * DD };
        for (int j = 0; j < 5; j++) {
            size_t off = (size_t)(i * 5 + j) * 65536;
            convert_w_kernel<<<cdiv(65536, 256), 256>>>(mats[j], p_whi + off, p_wlo + off, 256);
        }
    }
    size_t off_fq = WOFF_F, off_fk = WOFF_F + 16384, off_fv = WOFF_F + 32768;
    size_t off_fs = WOFF_F + 49152, off_fl = WOFF_F + 53248;
    convert_w_kernel<<<cdiv(16384, 256), 256>>>(fWq,   p_whi + off_fq, p_wlo + off_fq, 64);
    convert_w_kernel<<<cdiv(16384, 256), 256>>>(fWk,   p_whi + off_fk, p_wlo + off_fk, 64);
    convert_w_kernel<<<cdiv(16384, 256), 256>>>(fWv,   p_whi + off_fv, p_wlo + off_fv, 64);
    convert_w_kernel<<<cdiv(4096, 256), 256>>>(fWs,   p_whi + off_fs, p_wlo + off_fs, 16);
    convert_w_kernel<<<cdiv(4096, 256), 256>>>(flinW, p_whi + off_fl, p_wlo + off_fl, 16);

    // --- layer 0 input split ---
    convert_x_kernel<<<cdiv(N * DD, 256), 256>>>(x, p_hhi, p_hlo, N * DD);

    auto gemm = [&](const __nv_bfloat16* whi, const __nv_bfloat16* wlo,
                    const float* bias, float* Y, int m) {
        dim3 grid(cdiv(N, TBM), cdiv(m, 128));
        gemm_bf16x3_kernel<<<grid, 256, SMEM_WORDS * 4>>>(p_hhi, p_hlo, whi, wlo, bias, Y, N, m);
    };

    // --- 3 TransformerConv layers ---
    for (int i = 0; i < 3; i++) {
        size_t lb = (size_t)i * 5 * 65536;
        gemm(p_whi + lb,             p_wlo + lb,             bq + i * DD,   p_q,    DD);
        gemm(p_whi + lb + 65536,     p_wlo + lb + 65536,     bk + i * DD,   p_k,    DD);
        gemm(p_whi + lb + 2 * 65536, p_wlo + lb + 2 * 65536, bv + i * DD,   p_v,    DD);
        gemm(p_whi + lb + 3 * 65536, p_wlo + lb + 3 * 65536, bs + i * DD,   p_skip, DD);
        gemm(p_whi + lb + 4 * 65536, p_wlo + lb + 4 * 65536, linB + i * DD, p_lin,  DD);
        edge_attn_kernel<<<cdiv(N * 4 * 32, 256), 256>>>(p_q, p_k, p_v, p_rowptr, p_col, p_agg, N);
        combine_ln_kernel<<<cdiv(N * 32, 256), 256>>>(p_agg, p_skip, p_lin,
                                                      lnG + i * DD, lnB + i * DD,
                                                      p_hhi, p_hlo, N);
    }

    // --- final conv (HF=4, CLS=16, mean over heads) ---
    gemm(p_whi + off_fq, p_wlo + off_fq, fbq,   p_q,    64);
    gemm(p_whi + off_fk, p_wlo + off_fk, fbk,   p_k,    64);
    gemm(p_whi + off_fv, p_wlo + off_fv, fbv,   p_v,    64);
    gemm(p_whi + off_fs, p_wlo + off_fs, fbs,   p_skip, 16);
    gemm(p_whi + off_fl, p_wlo + off_fl, flinB, p_lin,  16);
    edge_attn_final_kernel<<<cdiv(N * 32, 256), 256>>>(p_q, p_k, p_v, p_rowptr, p_col, p_agg, N);
    final_combine_kernel<<<cdiv(N * 16, 256), 256>>>(p_agg, p_skip, p_lin, flnG, flnB, out, N);
}

// round 6
// speedup vs baseline: 2.7018x; 1.5100x over previous
#include <cuda_runtime.h>
#include <cuda_bf16.h>
#include <math_constants.h>
#include <stdint.h>

// Problem constants (fixed shapes per reference)
#define MAXN 50048
#define MAXE 400000
#define DD   256

// packed weight layout (rows are output-features, k contiguous):
//   layer i (i=0..2) at i*262144 : rows 0:256=Wq^T, 256:512=Wk^T, 512:768=Wv^T, 768:1024=(Ws+linW)^T
//   final at 786432 : rows 0:64=fWq^T, 64:128=fWk^T, 128:192=fWv^T, 192:208=(fWs+flinW)^T
#define WOFF_F   786432
#define WTOTAL   (WOFF_F + 208 * 256)
// packed bias: layer i at i*1024 (q|k|v|s+l), final at 3072 (208 entries)
#define BTOTAL   (3 * 1024 + 208)

// ---------------- scratch (static device globals; no allocs) ----------------
__device__ float g_big [MAXN * 1024];   // per-layer q|k|v|sl (stride 1024); final [N,208]
__device__ float g_agg [MAXN * DD];
__device__ __nv_bfloat16 g_hhi[MAXN * DD];
__device__ __nv_bfloat16 g_hlo[MAXN * DD];
__device__ __nv_bfloat16 g_whi[WTOTAL];
__device__ __nv_bfloat16 g_wlo[WTOTAL];
__device__ float g_bias[BTOTAL];
__device__ int   g_deg   [MAXN];
__device__ int   g_rowptr[MAXN + 1];
__device__ int   g_cursor[MAXN];
__device__ int   g_col   [MAXE];

// ---------------- CSR build ----------------
__global__ void zero_int_kernel(int* p, int n) {
    int i = blockIdx.x * blockDim.x + threadIdx.x;
    if (i < n) p[i] = 0;
}

__global__ void count_deg_kernel(const int* __restrict__ dst, int* deg, int E) {
    int i = blockIdx.x * blockDim.x + threadIdx.x;
    if (i < E) atomicAdd(&deg[dst[i]], 1);
}

__global__ void exscan_kernel(const int* __restrict__ deg, int* rowptr, int n) {
    __shared__ int warpsums[32];
    __shared__ int carry_s;
    int tid = threadIdx.x, lane = tid & 31, wid = tid >> 5;
    if (tid == 0) carry_s = 0;
    __syncthreads();
    for (int base = 0; base < n; base += 1024) {
        int carry = carry_s;
        int i = base + tid;
        int v = (i < n) ? deg[i] : 0;
        int x = v;
        #pragma unroll
        for (int o = 1; o < 32; o <<= 1) {
            int y = __shfl_up_sync(0xffffffffu, x, o);
            if (lane >= o) x += y;
        }
        if (lane == 31) warpsums[wid] = x;
        __syncthreads();
        if (wid == 0) {
            int s = warpsums[lane];
            #pragma unroll
            for (int o = 1; o < 32; o <<= 1) {
                int y = __shfl_up_sync(0xffffffffu, s, o);
                if (lane >= o) s += y;
            }
            warpsums[lane] = s;
        }
        __syncthreads();
        int block_excl = (wid > 0) ? warpsums[wid - 1] : 0;
        int incl = x + block_excl;
        if (i < n) rowptr[i] = carry + incl - v;
        int total = warpsums[31];
        __syncthreads();
        if (tid == 0) carry_s = carry + total;
        __syncthreads();
    }
    if (tid == 0) rowptr[n] = carry_s;
}

__global__ void copy_int_kernel(const int* __restrict__ a, int* b, int n) {
    int i = blockIdx.x * blockDim.x + threadIdx.x;
    if (i < n) b[i] = a[i];
}

__global__ void scatter_kernel(const int* __restrict__ src, const int* __restrict__ dst,
                               int* cursor, int* col, int E) {
    int i = blockIdx.x * blockDim.x + threadIdx.x;
    if (i < E) {
        int d = dst[i];
        int pos = atomicAdd(&cursor[d], 1);
        col[pos] = src[i];
    }
}

// ---------------- conversions ----------------
__device__ __forceinline__ void bf16_split(float f, __nv_bfloat16& h, __nv_bfloat16& l) {
    h = __float2bfloat16(f);
    l = __float2bfloat16(f - __bfloat162float(h));
}

__global__ void convert_x_kernel(const float* __restrict__ in,
                                 __nv_bfloat16* __restrict__ hi,
                                 __nv_bfloat16* __restrict__ lo, int n) {
    int i = blockIdx.x * blockDim.x + threadIdx.x;
    if (i < n) {
        __nv_bfloat16 h, l;
        bf16_split(in[i], h, l);
        hi[i] = h; lo[i] = l;
    }
}

struct WPtrs {
    const float *Wq, *Wk, *Wv, *Ws, *linW;       // [3][256,256] each (stacked)
    const float *fWq, *fWk, *fWv, *fWs, *flinW;  // [256,64] x3, [256,16] x2
};

// fused packed weight conversion: fp32 row-major [K=256, M] -> packed [rows, 256] hi/lo
__global__ void convert_weights_kernel(WPtrs p, __nv_bfloat16* __restrict__ hi,
                                       __nv_bfloat16* __restrict__ lo) {
    int idx = blockIdx.x * blockDim.x + threadIdx.x;
    if (idx >= WTOTAL) return;
    float val;
    if (idx < WOFF_F) {
        int layer = idx >> 18;          // /262144
        int rem = idx & 262143;
        int r = rem >> 8;               // packed row 0..1023
        int kk = rem & 255;
        int slot = r >> 8;              // 0..3
        int m = r & 255;
        size_t o = (size_t)layer * 65536 + (size_t)kk * 256 + m;
        if (slot == 0)      val = p.Wq[o];
        else if (slot == 1) val = p.Wk[o];
        else if (slot == 2) val = p.Wv[o];
        else                val = p.Ws[o] + p.linW[o];
    } else {
        int f = idx - WOFF_F;
        int r = f >> 8;                 // packed row 0..207
        int kk = f & 255;
        if (r < 64)       val = p.fWq[(size_t)kk * 64 + r];
        else if (r < 128) val = p.fWk[(size_t)kk * 64 + (r - 64)];
        else if (r < 192) val = p.fWv[(size_t)kk * 64 + (r - 128)];
        else              val = p.fWs[(size_t)kk * 16 + (r - 192)]
                              + p.flinW[(size_t)kk * 16 + (r - 192)];
    }
    __nv_bfloat16 h, l;
    bf16_split(val, h, l);
    hi[idx] = h; lo[idx] = l;
}

struct BPtrs {
    const float *bq, *bk, *bv, *bs, *linB;       // [3][256] each
    const float *fbq, *fbk, *fbv, *fbs, *flinB;  // [64]x3, [16]x2
};

__global__ void pack_bias_kernel(BPtrs p, float* __restrict__ out) {
    int idx = blockIdx.x * blockDim.x + threadIdx.x;
    if (idx >= BTOTAL) return;
    float val;
    if (idx < 3072) {
        int layer = idx >> 10;
        int r = idx & 1023;
        int slot = r >> 8;
        int c = r & 255;
        int o = layer * 256 + c;
        if (slot == 0)      val = p.bq[o];
        else if (slot == 1) val = p.bk[o];
        else if (slot == 2) val = p.bv[o];
        else                val = p.bs[o] + p.linB[o];
    } else {
        int f = idx - 3072;
        if (f < 64)       val = p.fbq[f];
        else if (f < 128) val = p.fbk[f - 64];
        else if (f < 192) val = p.fbv[f - 128];
        else              val = p.fbs[f - 192] + p.flinB[f - 192];
    }
    out[idx] = val;
}

// ---------------- cp.async helpers ----------------
__device__ __forceinline__ void cp16(uint32_t saddr, const void* gaddr, bool pred) {
    int sz = pred ? 16 : 0;
    asm volatile("cp.async.ca.shared.global [%0], [%1], 16, %2;\n"
                 :: "r"(saddr), "l"(gaddr), "r"(sz));
}
__device__ __forceinline__ void cp_commit() {
    asm volatile("cp.async.commit_group;\n" ::: "memory");
}
template <int NN>
__device__ __forceinline__ void cp_wait() {
    asm volatile("cp.async.wait_group %0;\n" :: "n"(NN) : "memory");
}

// ---------------- mma.sync bf16x3 GEMM ----------------
// Y[N, Mcols] = X[N,256] @ Wt^T + bias, X/W pre-split bf16 hi/lo, fp32 accum.
// Wt packed [Mcols, 256] (k contiguous). 128x128 tile, 256 thr = 8 warps (4Mx2N).
#define TBM    128
#define ROW_W  20
#define A_W    (128 * ROW_W)
#define SMEM_WORDS (8 * A_W)

__device__ __forceinline__ void mma_bf16(float c[4], uint32_t a0, uint32_t a1,
                                         uint32_t a2, uint32_t a3,
                                         uint32_t b0, uint32_t b1) {
    asm volatile(
        "mma.sync.aligned.m16n8k16.row.col.f32.bf16.bf16.f32 "
        "{%0,%1,%2,%3}, {%4,%5,%6,%7}, {%8,%9}, {%0,%1,%2,%3};\n"
        : "+f"(c[0]), "+f"(c[1]), "+f"(c[2]), "+f"(c[3])
        : "r"(a0), "r"(a1), "r"(a2), "r"(a3), "r"(b0), "r"(b1));
}

__global__ void __launch_bounds__(256, 2)
gemm_bf16x3_kernel(const __nv_bfloat16* __restrict__ Xhi, const __nv_bfloat16* __restrict__ Xlo,
                   const __nv_bfloat16* __restrict__ Whi, const __nv_bfloat16* __restrict__ Wlo,
                   const float* __restrict__ bias, float* __restrict__ Y,
                   int Nrows, int Mcols) {
    extern __shared__ uint32_t smw[];
    uint32_t base_u = (uint32_t)__cvta_generic_to_shared(smw);

    int tid = threadIdx.x;
    int lane = tid & 31, wid = tid >> 5;
    int rowTile = blockIdx.x * TBM;
    int colTile = blockIdx.y * 128;
    int warpRow = (wid & 3) * 32;
    int warpCol = (wid >> 2) * 64;

    float acc[2][8][4];
    #pragma unroll
    for (int mf = 0; mf < 2; mf++)
        #pragma unroll
        for (int nf = 0; nf < 8; nf++)
            #pragma unroll
            for (int i = 0; i < 4; i++) acc[mf][nf][i] = 0.f;

    auto stage = [&](int t, int buf) {
        int k0 = t * 32;
        #pragma unroll
        for (int i = 0; i < 2; i++) {
            int ch = tid + i * 256;
            int r = ch >> 2;
            int c = ch & 3;
            bool aok = (rowTile + r) < Nrows;
            size_t goff = (size_t)(rowTile + r) * 256 + k0 + c * 8;
            uint32_t soff = (uint32_t)(buf * A_W + r * ROW_W + c * 4) * 4u;
            cp16(base_u + soff, Xhi + goff, aok);
            cp16(base_u + (uint32_t)(2 * A_W) * 4u + soff, Xlo + goff, aok);
            bool bok = (colTile + r) < Mcols;
            size_t gboff = (size_t)(colTile + r) * 256 + k0 + c * 8;
            cp16(base_u + (uint32_t)(4 * A_W) * 4u + soff, Whi + gboff, bok);
            cp16(base_u + (uint32_t)(6 * A_W) * 4u + soff, Wlo + gboff, bok);
        }
        cp_commit();
    };

    stage(0, 0);

    const int NT = 8;
    for (int t = 0; t < NT; t++) {
        int buf = t & 1;
        if (t + 1 < NT) stage(t + 1, buf ^ 1);
        if (t + 1 < NT) cp_wait<1>(); else cp_wait<0>();
        __syncthreads();

        const uint32_t* AH = smw + buf * A_W;
        const uint32_t* AL = smw + 2 * A_W + buf * A_W;
        const uint32_t* BH = smw + 4 * A_W + buf * A_W;
        const uint32_t* BL = smw + 6 * A_W + buf * A_W;

        #pragma unroll
        for (int s = 0; s < 2; s++) {
            int kb = s * 8;
            uint32_t ahi[2][4], alo[2][4];
            #pragma unroll
            for (int mf = 0; mf < 2; mf++) {
                int r0 = warpRow + mf * 16 + (lane >> 2);
                int w0 = r0 * ROW_W + kb + (lane & 3);
                ahi[mf][0] = AH[w0];
                ahi[mf][1] = AH[w0 + 8 * ROW_W];
                ahi[mf][2] = AH[w0 + 4];
                ahi[mf][3] = AH[w0 + 4 + 8 * ROW_W];
                alo[mf][0] = AL[w0];
                alo[mf][1] = AL[w0 + 8 * ROW_W];
                alo[mf][2] = AL[w0 + 4];
                alo[mf][3] = AL[w0 + 4 + 8 * ROW_W];
            }
            #pragma unroll
            for (int nf = 0; nf < 8; nf++) {
                int n = warpCol + nf * 8 + (lane >> 2);
                int wb = n * ROW_W + kb + (lane & 3);
                uint32_t bh0 = BH[wb], bh1 = BH[wb + 4];
                uint32_t bl0 = BL[wb], bl1 = BL[wb + 4];
                #pragma unroll
                for (int mf = 0; mf < 2; mf++) {
                    mma_bf16(acc[mf][nf], ahi[mf][0], ahi[mf][1], ahi[mf][2], ahi[mf][3], bh0, bh1);
                    mma_bf16(acc[mf][nf], ahi[mf][0], ahi[mf][1], ahi[mf][2], ahi[mf][3], bl0, bl1);
                    mma_bf16(acc[mf][nf], alo[mf][0], alo[mf][1], alo[mf][2], alo[mf][3], bh0, bh1);
                }
            }
        }
        __syncthreads();
    }

    #pragma unroll
    for (int mf = 0; mf < 2; mf++) {
        #pragma unroll
        for (int nf = 0; nf < 8; nf++) {
            int col = colTile + warpCol + nf * 8 + 2 * (lane & 3);
            if (col >= Mcols) continue;
            float bx = bias[col], by = bias[col + 1];
            int r0 = rowTile + warpRow + mf * 16 + (lane >> 2);
            if (r0 < Nrows) {
                float2 o = make_float2(acc[mf][nf][0] + bx, acc[mf][nf][1] + by);
                *(float2*)&Y[(size_t)r0 * Mcols + col] = o;
            }
            int r1 = r0 + 8;
            if (r1 < Nrows) {
                float2 o = make_float2(acc[mf][nf][2] + bx, acc[mf][nf][3] + by);
                *(float2*)&Y[(size_t)r1 * Mcols + col] = o;
            }
        }
    }
}

// ---------------- edge attention (layers): warp per node, all 4 heads ----------------
// big row layout: [q(0:256) | k(256:512) | v(512:768) | sl(768:1024)]
// lane l owns channels [8l, 8l+8) (head = l>>3); 8-lane xor reduce gives head dot.
__global__ void edge_attn_kernel(const float* __restrict__ big,
                                 const int* __restrict__ rowptr, const int* __restrict__ col,
                                 float* __restrict__ agg, int Nn) {
    int node = (blockIdx.x * blockDim.x + threadIdx.x) >> 5;
    int lane = threadIdx.x & 31;
    if (node >= Nn) return;
    const float* qrow = big + (size_t)node * 1024 + lane * 8;
    float4 qa = *(const float4*)qrow;
    float4 qb = *(const float4*)(qrow + 4);
    int e0 = rowptr[node], e1 = rowptr[node + 1];
    float m = -CUDART_INF_F, ssum = 0.f;
    float4 acca = make_float4(0.f, 0.f, 0.f, 0.f);
    float4 accb = make_float4(0.f, 0.f, 0.f, 0.f);
    for (int e = e0; e < e1; e++) {
        int src = col[e];
        const float* kr = big + (size_t)src * 1024 + 256 + lane * 8;
        float4 ka = *(const float4*)kr;
        float4 kb = *(const float4*)(kr + 4);
        const float* vr = big + (size_t)src * 1024 + 512 + lane * 8;
        float4 va = *(const float4*)vr;
        float4 vb = *(const float4*)(vr + 4);
        float part = qa.x * ka.x + qa.y * ka.y + qa.z * ka.z + qa.w * ka.w
                   + qb.x * kb.x + qb.y * kb.y + qb.z * kb.z + qb.w * kb.w;
        part += __shfl_xor_sync(0xffffffffu, part, 1);
        part += __shfl_xor_sync(0xffffffffu, part, 2);
        part += __shfl_xor_sync(0xffffffffu, part, 4);
        float score = part * 0.125f;           // 1/sqrt(64)
        float newm = fmaxf(m, score);
        float scale = __expf(m - newm);
        float pr = __expf(score - newm);
        ssum = ssum * scale + pr;
        acca.x = acca.x * scale + pr * va.x;
        acca.y = acca.y * scale + pr * va.y;
        acca.z = acca.z * scale + pr * va.z;
        acca.w = acca.w * scale + pr * va.w;
        accb.x = accb.x * scale + pr * vb.x;
        accb.y = accb.y * scale + pr * vb.y;
        accb.z = accb.z * scale + pr * vb.z;
        accb.w = accb.w * scale + pr * vb.w;
        m = newm;
    }
    float inv = (ssum > 0.f) ? (1.f / ssum) : 0.f;
    acca.x *= inv; acca.y *= inv; acca.z *= inv; acca.w *= inv;
    accb.x *= inv; accb.y *= inv; accb.z *= inv; accb.w *= inv;
    float* arow = agg + (size_t)node * 256 + lane * 8;
    *(float4*)arow = acca;
    *(float4*)(arow + 4) = accb;
}

// ---------------- combine + elu + layernorm -> split bf16 hi/lo ----------------
__global__ void combine_ln_kernel(const float* __restrict__ agg, const float* __restrict__ big,
                                  const float* __restrict__ g, const float* __restrict__ b,
                                  __nv_bfloat16* __restrict__ hhi,
                                  __nv_bfloat16* __restrict__ hlo, int Nn) {
    int node = (blockIdx.x * blockDim.x + threadIdx.x) >> 5;
    int lane = threadIdx.x & 31;
    if (node >= Nn) return;
    int base = node * 256;
    const float* sl = big + (size_t)node * 1024 + 768;
    float t[8];
    float sum = 0.f;
    #pragma unroll
    for (int r = 0; r < 8; r++) {
        int j = r * 32 + lane;
        float c = agg[base + j] + sl[j];
        float e = (c > 0.f) ? c : expm1f(c);
        t[r] = e; sum += e;
    }
    #pragma unroll
    for (int o = 16; o > 0; o >>= 1) sum += __shfl_xor_sync(0xffffffffu, sum, o);
    float mu = sum * (1.f / 256.f);
    float var = 0.f;
    #pragma unroll
    for (int r = 0; r < 8; r++) { float d = t[r] - mu; var += d * d; }
    #pragma unroll
    for (int o = 16; o > 0; o >>= 1) var += __shfl_xor_sync(0xffffffffu, var, o);
    var *= (1.f / 256.f);
    float inv = rsqrtf(var + 1e-5f);
    #pragma unroll
    for (int r = 0; r < 8; r++) {
        int j = r * 32 + lane;
        float val = (t[r] - mu) * inv * g[j] + b[j];
        __nv_bfloat16 h, l;
        bf16_split(val, h, l);
        hhi[base + j] = h;
        hlo[base + j] = l;
    }
}

// ---------------- final edge attention: warp per node; HF=4 heads, C=16 ch ----------------
// big208 row: [q(0:64) | k(64:128) | v(128:192) | sl(192:208)], stride 208
__global__ void edge_attn_final_kernel(const float* __restrict__ big,
                                       const int* __restrict__ rowptr, const int* __restrict__ col,
                                       float* __restrict__ agg, int Nn) {
    int node = (blockIdx.x * blockDim.x + threadIdx.x) >> 5;
    int lane = threadIdx.x & 31;
    if (node >= Nn) return;
    float2 q2 = *(const float2*)(big + (size_t)node * 208 + lane * 2);
    int e0 = rowptr[node], e1 = rowptr[node + 1];
    float m = -CUDART_INF_F, ssum = 0.f;
    float2 acc = make_float2(0.f, 0.f);
    for (int e = e0; e < e1; e++) {
        int src = col[e];
        const float* srow = big + (size_t)src * 208;
        float2 k2 = *(const float2*)(srow + 64 + lane * 2);
        float2 v2 = *(const float2*)(srow + 128 + lane * 2);
        float part = q2.x * k2.x + q2.y * k2.y;
        part += __shfl_xor_sync(0xffffffffu, part, 1);
        part += __shfl_xor_sync(0xffffffffu, part, 2);
        part += __shfl_xor_sync(0xffffffffu, part, 4);
        float score = part * 0.25f;            // 1/sqrt(16)
        float newm = fmaxf(m, score);
        float scale = __expf(m - newm);
        float pr = __expf(score - newm);
        ssum = ssum * scale + pr;
        acc.x = acc.x * scale + pr * v2.x;
        acc.y = acc.y * scale + pr * v2.y;
        m = newm;
    }
    float inv = (ssum > 0.f) ? (1.f / ssum) : 0.f;
    acc.x *= inv; acc.y *= inv;
    *(float2*)(agg + (size_t)node * 64 + lane * 2) = acc;
}

// ---------------- final combine: mean heads + sl + LN(16) ----------------
__global__ void final_combine_kernel(const float* __restrict__ aggF, const float* __restrict__ big,
                                     const float* __restrict__ g, const float* __restrict__ b,
                                     float* __restrict__ out, int Nn) {
    int t = blockIdx.x * blockDim.x + threadIdx.x;
    int node = t >> 4;
    int c = t & 15;
    if (node >= Nn) return;
    const float* ar = aggF + (size_t)node * 64;
    float val = 0.25f * (ar[c] + ar[16 + c] + ar[32 + c] + ar[48 + c])
              + big[(size_t)node * 208 + 192 + c];
    float sum = val;
    #pragma unroll
    for (int o = 8; o > 0; o >>= 1) sum += __shfl_xor_sync(0xffffffffu, sum, o);
    float mu = sum * (1.f / 16.f);
    float d = val - mu;
    float var = d * d;
    #pragma unroll
    for (int o = 8; o > 0; o >>= 1) var += __shfl_xor_sync(0xffffffffu, var, o);
    var *= (1.f / 16.f);
    out[node * 16 + c] = (val - mu) * rsqrtf(var + 1e-5f) * g[c] + b[c];
}

// ---------------- host launch ----------------
static inline int cdiv(int a, int b) { return (a + b - 1) / b; }

extern "C" void kernel_launch(void* const* d_in, const int* in_sizes, int n_in,
                              void* d_out, int out_size) {
    const float* x    = (const float*)d_in[0];
    const int*   ei   = (const int*)  d_in[1];
    const float* Wq   = (const float*)d_in[2];
    const float* bq   = (const float*)d_in[3];
    const float* Wk   = (const float*)d_in[4];
    const float* bk   = (const float*)d_in[5];
    const float* Wv   = (const float*)d_in[6];
    const float* bv   = (const float*)d_in[7];
    const float* Ws   = (const float*)d_in[8];
    const float* bs   = (const float*)d_in[9];
    const float* lnG  = (const float*)d_in[10];
    const float* lnB  = (const float*)d_in[11];
    const float* linW = (const float*)d_in[12];
    const float* linB = (const float*)d_in[13];
    const float* fWq  = (const float*)d_in[14];
    const float* fbq  = (const float*)d_in[15];
    const float* fWk  = (const float*)d_in[16];
    const float* fbk  = (const float*)d_in[17];
    const float* fWv  = (const float*)d_in[18];
    const float* fbv  = (const float*)d_in[19];
    const float* fWs  = (const float*)d_in[20];
    const float* fbs  = (const float*)d_in[21];
    const float* flnG = (const float*)d_in[22];
    const float* flnB = (const float*)d_in[23];
    const float* flinW= (const float*)d_in[24];
    const float* flinB= (const float*)d_in[25];
    float* out = (float*)d_out;

    int N = in_sizes[0] / DD;     // 50000
    int E = in_sizes[1] / 2;      // 400000

    cudaFuncSetAttribute(gemm_bf16x3_kernel,
                         cudaFuncAttributeMaxDynamicSharedMemorySize, SMEM_WORDS * 4);

    float *p_big, *p_agg, *p_bias;
    __nv_bfloat16 *p_hhi, *p_hlo, *p_whi, *p_wlo;
    int *p_deg, *p_rowptr, *p_cursor, *p_col;
    cudaGetSymbolAddress((void**)&p_big,  g_big);
    cudaGetSymbolAddress((void**)&p_agg,  g_agg);
    cudaGetSymbolAddress((void**)&p_bias, g_bias);
    cudaGetSymbolAddress((void**)&p_hhi,  g_hhi);
    cudaGetSymbolAddress((void**)&p_hlo,  g_hlo);
    cudaGetSymbolAddress((void**)&p_whi,  g_whi);
    cudaGetSymbolAddress((void**)&p_wlo,  g_wlo);
    cudaGetSymbolAddress((void**)&p_deg,    g_deg);
    cudaGetSymbolAddress((void**)&p_rowptr, g_rowptr);
    cudaGetSymbolAddress((void**)&p_cursor, g_cursor);
    cudaGetSymbolAddress((void**)&p_col,    g_col);

    const int* src = ei;
    const int* dst = ei + E;

    // --- CSR build (by dst) ---
    zero_int_kernel<<<cdiv(N, 256), 256>>>(p_deg, N);
    count_deg_kernel<<<cdiv(E, 256), 256>>>(dst, p_deg, E);
    exscan_kernel<<<1, 1024>>>(p_deg, p_rowptr, N);
    copy_int_kernel<<<cdiv(N, 256), 256>>>(p_rowptr, p_cursor, N);
    scatter_kernel<<<cdiv(E, 256), 256>>>(src, dst, p_cursor, p_col, E);

    // --- fused weight + bias conversion ---
    WPtrs wp = { Wq, Wk, Wv, Ws, linW, fWq, fWk, fWv, fWs, flinW };
    convert_weights_kernel<<<cdiv(WTOTAL, 256), 256>>>(wp, p_whi, p_wlo);
    BPtrs bp = { bq, bk, bv, bs, linB, fbq, fbk, fbv, fbs, flinB };
    pack_bias_kernel<<<cdiv(BTOTAL, 256), 256>>>(bp, p_bias);

    // --- layer 0 input split ---
    convert_x_kernel<<<cdiv(N * DD, 256), 256>>>(x, p_hhi, p_hlo, N * DD);

    // --- 3 TransformerConv layers ---
    for (int i = 0; i < 3; i++) {
        dim3 grid(cdiv(N, TBM), 8);   // Mcols = 1024 packed q|k|v|sl
        gemm_bf16x3_kernel<<<grid, 256, SMEM_WORDS * 4>>>(
            p_hhi, p_hlo,
            p_whi + (size_t)i * 262144, p_wlo + (size_t)i * 262144,
            p_bias + i * 1024, p_big, N, 1024);
        edge_attn_kernel<<<cdiv(N * 32, 256), 256>>>(p_big, p_rowptr, p_col, p_agg, N);
        combine_ln_kernel<<<cdiv(N * 32, 256), 256>>>(p_agg, p_big,
                                                      lnG + i * DD, lnB + i * DD,
                                                      p_hhi, p_hlo, N);
    }

    // --- final conv (packed [N,208]: q|k|v|sl) ---
    {
        dim3 grid(cdiv(N, TBM), 2);
        gemm_bf16x3_kernel<<<grid, 256, SMEM_WORDS * 4>>>(
            p_hhi, p_hlo, p_whi + WOFF_F, p_wlo + WOFF_F,
            p_bias + 3072, p_big, N, 208);
    }
    edge_attn_final_kernel<<<cdiv(N * 32, 256), 256>>>(p_big, p_rowptr, p_col, p_agg, N);
    final_combine_kernel<<<cdiv(N * 16, 256), 256>>>(p_agg, p_big, flnG, flnB, out, N);
}